// round 10
// baseline (speedup 1.0000x reference)
#include <cuda_runtime.h>
#include <cuda_fp16.h>
#include <cstdint>

// ---------------------------------------------------------------------------
// out[M,N] = segment_mean(gather(cf, member_idx), segment_ids) @ W + b
// R10: claim-based fused kernel. Grid = ntm*4 GEMM CTAs (bid = bn*ntm + m,
// m fastest). First CTA to touch M-tile m (atomicCAS) computes its 128 means
// into g_a (fp16) itself, then GEMMs; others spin till flag==2 then GEMM.
// Wave 1 = 296 claimers (no spinners), gather overlaps GEMM across waves.
// Prelude: starts[]+flag reset, W transpose->fp16.
// ---------------------------------------------------------------------------

#define MAX_ROWS_PAD 65664
#define AK 256

__device__ __half g_a[(size_t)MAX_ROWS_PAD * AK];
__device__ __half g_b[1024 * 512];          // [N][K] (W transposed)
__device__ int g_starts[65600];
__device__ int g_flag[512];

// ---------------------------------------------------------------------------
// PTX helpers (baseline sm_80 features — safe through compute_103 PTX)
// ---------------------------------------------------------------------------
__device__ __forceinline__ uint32_t smem_u32(const void* p) {
    uint32_t a;
    asm("{ .reg .u64 t; cvta.to.shared.u64 t, %1; cvt.u32.u64 %0, t; }"
        : "=r"(a) : "l"(p));
    return a;
}

#define CP16(dst, src) \
    asm volatile("cp.async.cg.shared.global [%0], [%1], 16;" \
                 :: "r"(dst), "l"(src) : "memory")
#define CP_COMMIT() asm volatile("cp.async.commit_group;" ::: "memory")
#define CP_WAIT1()  asm volatile("cp.async.wait_group 1;" ::: "memory")

#define LDM4(r, a) \
    asm volatile("ldmatrix.sync.aligned.m8n8.x4.shared.b16 {%0,%1,%2,%3}, [%4];" \
                 : "=r"((r)[0]), "=r"((r)[1]), "=r"((r)[2]), "=r"((r)[3]) \
                 : "r"(a))

#define MMA_F16(d, a, b0, b1) \
    asm volatile("mma.sync.aligned.m16n8k16.row.col.f32.f16.f16.f32 " \
                 "{%0,%1,%2,%3}, {%4,%5,%6,%7}, {%8,%9}, {%0,%1,%2,%3};" \
                 : "+f"((d)[0]), "+f"((d)[1]), "+f"((d)[2]), "+f"((d)[3]) \
                 : "r"((a)[0]), "r"((a)[1]), "r"((a)[2]), "r"((a)[3]), \
                   "r"(b0), "r"(b1))

#define ACC4(a, v) { (a).x += (v).x; (a).y += (v).y; (a).z += (v).z; (a).w += (v).w; }

// ---------------------------------------------------------------------------
// Kernel 0: segment starts + flag reset
// ---------------------------------------------------------------------------
__global__ void starts_kernel(const int* __restrict__ seg, int num_members, int num_cells) {
    int i = blockIdx.x * blockDim.x + threadIdx.x;
    if (i < 512) g_flag[i] = 0;
    if (i > num_members) return;
    int cur  = (i < num_members) ? __ldg(&seg[i]) : num_cells;
    int prev = (i > 0) ? __ldg(&seg[i - 1]) : -1;
    for (int c = prev + 1; c <= cur; c++) g_starts[c] = i;
}

// ---------------------------------------------------------------------------
// Kernel 1: W prepack -> [N][K] fp16 via smem-tiled transpose
// ---------------------------------------------------------------------------
__global__ void prepw_kernel(const float* __restrict__ W, int K, int N) {
    __shared__ float t[32][33];
    const int kb = blockIdx.x * 32, nb = blockIdx.y * 32;
    const int tx = threadIdx.x, ty = threadIdx.y;
#pragma unroll
    for (int i = 0; i < 4; i++)
        t[ty + i * 8][tx] = W[(size_t)(kb + ty + i * 8) * N + nb + tx];
    __syncthreads();
#pragma unroll
    for (int i = 0; i < 4; i++)
        g_b[(size_t)(nb + ty + i * 8) * K + kb + tx] =
            __float2half_rn(t[tx][ty + i * 8]);
}

// ---------------------------------------------------------------------------
// Fused claim kernel. 256 threads, 96KB smem, 2 CTAs/SM.
// ---------------------------------------------------------------------------
#define STAGE_BYTES 32768u
#define SEC_BYTES   16384u
#define NSTAGE      3

__global__ __launch_bounds__(256, 2)
void fused_kernel(const float4* __restrict__ cf4,
                  const int* __restrict__ midx,
                  const float* __restrict__ bias,
                  float* __restrict__ C,
                  int M, int N, int K, int ntm) {
    extern __shared__ char smem[];
    const int tid = threadIdx.x;
    const int m_t = blockIdx.x % ntm;      // m fastest -> first ntm bids claim
    const int n_t = blockIdx.x / ntm;
    const int bm  = m_t * 128, bn = n_t * 128;
    const int K4  = K >> 2;

    __shared__ int s_role;                 // 1 = claimer, 0 = waiter, 2 = done
    if (tid == 0) {
        int old = atomicCAS(&g_flag[m_t], 0, 1);
        s_role = (old == 0) ? 1 : ((old == 2) ? 2 : 0);
    }
    __syncthreads();
    const int role = s_role;

    if (role == 1) {
        // ---- claimer: compute means of cells [bm, bm+128) into g_a ----
        const int grp = tid >> 6;          // 0..3 (4 cells in parallel)
        const int l64 = tid & 63;          // float4 chunk of the 256-dim row
#pragma unroll 1
        for (int i = 0; i < 32; i++) {
            const int c = bm + grp * 32 + i;
            const int start = __ldg(&g_starts[c]);
            const int end   = __ldg(&g_starts[c + 1]);

            float4 a0 = make_float4(0.f, 0.f, 0.f, 0.f);
            float4 a1 = a0, a2 = a0, a3 = a0;
            int j = start;
            for (; j + 4 <= end; j += 4) {
                int i0 = __ldg(&midx[j])     * K4;
                int i1 = __ldg(&midx[j + 1]) * K4;
                int i2 = __ldg(&midx[j + 2]) * K4;
                int i3 = __ldg(&midx[j + 3]) * K4;
                float4 v0 = cf4[(size_t)i0 + l64];
                float4 v1 = cf4[(size_t)i1 + l64];
                float4 v2 = cf4[(size_t)i2 + l64];
                float4 v3 = cf4[(size_t)i3 + l64];
                ACC4(a0, v0); ACC4(a1, v1); ACC4(a2, v2); ACC4(a3, v3);
            }
            for (; j < end; j++) {
                int i0 = __ldg(&midx[j]) * K4;
                float4 v0 = cf4[(size_t)i0 + l64];
                ACC4(a0, v0);
            }

            const float inv = 1.0f / fmaxf((float)(end - start), 1.0f);
            __half2 h0 = __floats2half2_rn((a0.x + a1.x + a2.x + a3.x) * inv,
                                           (a0.y + a1.y + a2.y + a3.y) * inv);
            __half2 h1 = __floats2half2_rn((a0.z + a1.z + a2.z + a3.z) * inv,
                                           (a0.w + a1.w + a2.w + a3.w) * inv);
            uint2 pk;
            pk.x = *(uint32_t*)&h0;
            pk.y = *(uint32_t*)&h1;
            ((uint2*)g_a)[(size_t)c * K4 + l64] = pk;
        }
        __threadfence();                   // publish g_a writes (all threads)
        __syncthreads();
        if (tid == 0) atomicExch(&g_flag[m_t], 2);
    } else if (role != 2) {
        // ---- waiter: spin until tile means are published ----
        if (tid == 0) {
            while (atomicAdd(&g_flag[m_t], 0) != 2) __nanosleep(128);
            __threadfence();
        }
    }
    __syncthreads();

    // ---------------- GEMM (R6 body) ----------------
    const uint32_t sb = smem_u32(smem);
    const int wid  = tid >> 5, lane = tid & 31;
    const int wm   = wid & 3;
    const int wn   = wid >> 2;
    const size_t rowb = (size_t)K * 2;

    const char* pA = (const char*)g_a + (size_t)bm * rowb;
    const char* pB = (const char*)g_b + (size_t)bn * rowb;

    uint32_t sdst[4];
    int lrow[4], lch[4];
#pragma unroll
    for (int i = 0; i < 4; i++) {
        int idx = i * 256 + tid;
        lrow[i] = idx >> 3;
        lch[i]  = idx & 7;
        sdst[i] = (uint32_t)(lrow[i] * 128 + ((lch[i] ^ (lrow[i] & 7)) << 4));
    }

    float acc[2][8][4];
#pragma unroll
    for (int g = 0; g < 2; g++)
#pragma unroll
        for (int n = 0; n < 8; n++)
#pragma unroll
            for (int j = 0; j < 4; j++) acc[g][n][j] = 0.f;

    const int a_r = (lane & 15);
    const int a_cadd = (lane >> 4);
    const int b_r = (lane & 7) + ((lane >> 4) << 3);
    const int b_cadd = ((lane >> 3) & 1);

    const int nit = K >> 6;

#pragma unroll
    for (int pre = 0; pre < 2; pre++) {
        const uint32_t sbase = sb + (uint32_t)pre * STAGE_BYTES;
        const size_t kt = (size_t)pre * 128;
#pragma unroll
        for (int i = 0; i < 4; i++) {
            CP16(sbase + sdst[i],             pA + (size_t)lrow[i] * rowb + kt + lch[i] * 16);
            CP16(sbase + SEC_BYTES + sdst[i], pB + (size_t)lrow[i] * rowb + kt + lch[i] * 16);
        }
        CP_COMMIT();
    }

    for (int it = 0; it < nit; it++) {
        const uint32_t stg = sb + (uint32_t)(it % NSTAGE) * STAGE_BYTES;
        CP_WAIT1();
        __syncthreads();

        if (it + 2 < nit) {
            const uint32_t sbase = sb + (uint32_t)((it + 2) % NSTAGE) * STAGE_BYTES;
            const size_t kt = (size_t)(it + 2) * 128;
#pragma unroll
            for (int i = 0; i < 4; i++) {
                CP16(sbase + sdst[i],             pA + (size_t)lrow[i] * rowb + kt + lch[i] * 16);
                CP16(sbase + SEC_BYTES + sdst[i], pB + (size_t)lrow[i] * rowb + kt + lch[i] * 16);
            }
            CP_COMMIT();
        } else {
            CP_COMMIT();
        }

#pragma unroll
        for (int s = 0; s < 4; s++) {
            uint32_t af[2][4];
#pragma unroll
            for (int g = 0; g < 2; g++) {
                int row = wm * 32 + g * 16 + a_r;
                int ch  = s * 2 + a_cadd;
                LDM4(af[g], stg + row * 128 + ((ch ^ (row & 7)) << 4));
            }
            uint32_t bf[4][4];
#pragma unroll
            for (int h = 0; h < 4; h++) {
                int row = wn * 64 + h * 16 + b_r;
                int ch  = s * 2 + b_cadd;
                LDM4(bf[h], stg + SEC_BYTES + row * 128 + ((ch ^ (row & 7)) << 4));
            }
#pragma unroll
            for (int h = 0; h < 4; h++)
#pragma unroll
                for (int g = 0; g < 2; g++) {
                    MMA_F16(acc[g][h * 2],     af[g], bf[h][0], bf[h][1]);
                    MMA_F16(acc[g][h * 2 + 1], af[g], bf[h][2], bf[h][3]);
                }
        }
        __syncthreads();
    }

#pragma unroll
    for (int g = 0; g < 2; g++) {
        int row0 = bm + wm * 32 + g * 16 + (lane >> 2);
        int row1 = row0 + 8;
#pragma unroll
        for (int n = 0; n < 8; n++) {
            int col = bn + wn * 64 + n * 8 + (lane & 3) * 2;
            float2 bb = *(const float2*)&bias[col];
            if (row0 < M) {
                float2 o = make_float2(acc[g][n][0] + bb.x, acc[g][n][1] + bb.y);
                *(float2*)&C[(size_t)row0 * N + col] = o;
            }
            if (row1 < M) {
                float2 o = make_float2(acc[g][n][2] + bb.x, acc[g][n][3] + bb.y);
                *(float2*)&C[(size_t)row1 * N + col] = o;
            }
        }
    }
}

// ---------------------------------------------------------------------------
// Launch
// ---------------------------------------------------------------------------
extern "C" void kernel_launch(void* const* d_in, const int* in_sizes, int n_in,
                              void* d_out, int out_size) {
    const float* cf   = (const float*)d_in[0];
    const int* midx   = (const int*)d_in[1];
    const int* seg    = (const int*)d_in[2];
    const float* W    = (const float*)d_in[4];
    const float* bias = (const float*)d_in[5];
    float* out = (float*)d_out;

    const int N = in_sizes[5];           // 512
    const int K = in_sizes[4] / N;       // 256
    const int M = out_size / N;          // 50000
    const int num_members = in_sizes[1]; // 400000
    const int ntm = (M + 127) / 128;     // 391 M-tiles

    cudaFuncSetAttribute(fused_kernel,
                         cudaFuncAttributeMaxDynamicSharedMemorySize,
                         (int)(NSTAGE * STAGE_BYTES));

    starts_kernel<<<(num_members + 256) / 256, 256>>>(seg, num_members, M);
    dim3 tb(32, 8), tg(K / 32, N / 32);
    prepw_kernel<<<tg, tb>>>(W, K, N);

    fused_kernel<<<ntm * (N / 128), 256, NSTAGE * STAGE_BYTES>>>(
        (const float4*)cf, midx, bias, out, M, N, K, ntm);
}

// round 11
// speedup vs baseline: 1.7196x; 1.7196x over previous
#include <cuda_runtime.h>
#include <cuda_fp16.h>
#include <cstdint>

// ---------------------------------------------------------------------------
// out[M,N] = segment_mean(gather(cf, member_idx), segment_ids) @ W + b
// R11: R6 structure (best known: split kernels) + three micro-wins:
//   (1) mean kernel unroll-4 (4 independent acc chains, higher gather MLP)
//   (2) GEMM mainloop: drop redundant trailing __syncthreads
//   (3) starts + W-prepack merged into one prep kernel (one less launch)
// GEMM: fp16 mma.sync, CTA 128x128, BK=64, 3-stage cp.async, 2 CTAs/SM.
// ---------------------------------------------------------------------------

#define MAX_ROWS_PAD 65664          // multiple of 128, >= padded M
#define AK 256

// Zero-initialized scratch. Rows >= M never written -> stay zero (no guards).
__device__ __half g_a[(size_t)MAX_ROWS_PAD * AK];
__device__ __half g_b[1024 * 512];          // [N][K] (W transposed)
__device__ int g_starts[65600];

// ---------------------------------------------------------------------------
// PTX helpers (baseline sm_80 features — safe through compute_103 PTX)
// ---------------------------------------------------------------------------
__device__ __forceinline__ uint32_t smem_u32(const void* p) {
    uint32_t a;
    asm("{ .reg .u64 t; cvta.to.shared.u64 t, %1; cvt.u32.u64 %0, t; }"
        : "=r"(a) : "l"(p));
    return a;
}

#define CP16(dst, src) \
    asm volatile("cp.async.cg.shared.global [%0], [%1], 16;" \
                 :: "r"(dst), "l"(src) : "memory")
#define CP_COMMIT() asm volatile("cp.async.commit_group;" ::: "memory")
#define CP_WAIT1()  asm volatile("cp.async.wait_group 1;" ::: "memory")

#define LDM4(r, a) \
    asm volatile("ldmatrix.sync.aligned.m8n8.x4.shared.b16 {%0,%1,%2,%3}, [%4];" \
                 : "=r"((r)[0]), "=r"((r)[1]), "=r"((r)[2]), "=r"((r)[3]) \
                 : "r"(a))

#define MMA_F16(d, a, b0, b1) \
    asm volatile("mma.sync.aligned.m16n8k16.row.col.f32.f16.f16.f32 " \
                 "{%0,%1,%2,%3}, {%4,%5,%6,%7}, {%8,%9}, {%0,%1,%2,%3};" \
                 : "+f"((d)[0]), "+f"((d)[1]), "+f"((d)[2]), "+f"((d)[3]) \
                 : "r"((a)[0]), "r"((a)[1]), "r"((a)[2]), "r"((a)[3]), \
                   "r"(b0), "r"(b1))

#define ACC4(a, v) { (a).x += (v).x; (a).y += (v).y; (a).z += (v).z; (a).w += (v).w; }

// ---------------------------------------------------------------------------
// Kernel 0: prep = segment starts (blocks [0, nbs)) + W prepack (rest).
// ---------------------------------------------------------------------------
__global__ void prep_kernel(const int* __restrict__ seg, int num_members, int num_cells,
                            const float* __restrict__ W, int K, int N, int nbs) {
    const int bid = blockIdx.x;
    if (bid < nbs) {
        int i = bid * 256 + threadIdx.x;
        if (i > num_members) return;
        int cur  = (i < num_members) ? __ldg(&seg[i]) : num_cells;
        int prev = (i > 0) ? __ldg(&seg[i - 1]) : -1;
        for (int c = prev + 1; c <= cur; c++) g_starts[c] = i;
        return;
    }
    // ---- W transpose tile (32x32), fp16 out ----
    __shared__ float t[32][33];
    const int b2 = bid - nbs;
    const int ktiles = K >> 5;
    const int kb = (b2 % ktiles) * 32, nb = (b2 / ktiles) * 32;
    const int tx = threadIdx.x & 31, ty = threadIdx.x >> 5;   // 32 x 8
#pragma unroll
    for (int i = 0; i < 4; i++)
        t[ty + i * 8][tx] = W[(size_t)(kb + ty + i * 8) * N + nb + tx];
    __syncthreads();
#pragma unroll
    for (int i = 0; i < 4; i++)
        g_b[(size_t)(nb + ty + i * 8) * K + kb + tx] =
            __float2half_rn(t[tx][ty + i * 8]);
}

// ---------------------------------------------------------------------------
// Kernel 1: segment mean -> fp16. 128 threads = 2 cells per block (64 each).
// Thread t owns float4 chunk t. Index loads are uniform broadcasts.
// Unroll-4: four independent accumulator chains for gather MLP.
// ---------------------------------------------------------------------------
__global__ void mean_kernel(const float4* __restrict__ cf4,
                            const int* __restrict__ midx,
                            int K4, int M) {
    const int c = blockIdx.x * 2 + (threadIdx.x >> 6);
    if (c >= M) return;
    const int tid = threadIdx.x & 63;
    const int start = __ldg(&g_starts[c]);
    const int end   = __ldg(&g_starts[c + 1]);

    float4 a0 = make_float4(0.f, 0.f, 0.f, 0.f);
    float4 a1 = a0, a2 = a0, a3 = a0;

    int j = start;
    for (; j + 4 <= end; j += 4) {
        int i0 = __ldg(&midx[j])     * K4;
        int i1 = __ldg(&midx[j + 1]) * K4;
        int i2 = __ldg(&midx[j + 2]) * K4;
        int i3 = __ldg(&midx[j + 3]) * K4;
        float4 v0 = cf4[(size_t)i0 + tid];
        float4 v1 = cf4[(size_t)i1 + tid];
        float4 v2 = cf4[(size_t)i2 + tid];
        float4 v3 = cf4[(size_t)i3 + tid];
        ACC4(a0, v0); ACC4(a1, v1); ACC4(a2, v2); ACC4(a3, v3);
    }
    for (; j < end; j++) {
        int i0 = __ldg(&midx[j]) * K4;
        float4 v0 = cf4[(size_t)i0 + tid];
        ACC4(a0, v0);
    }

    float inv = 1.0f / fmaxf((float)(end - start), 1.0f);
    __half2 h0 = __floats2half2_rn((a0.x + a1.x + a2.x + a3.x) * inv,
                                   (a0.y + a1.y + a2.y + a3.y) * inv);
    __half2 h1 = __floats2half2_rn((a0.z + a1.z + a2.z + a3.z) * inv,
                                   (a0.w + a1.w + a2.w + a3.w) * inv);
    uint2 pk;
    pk.x = *(uint32_t*)&h0;
    pk.y = *(uint32_t*)&h1;
    ((uint2*)g_a)[(size_t)c * K4 + tid] = pk;
}

// ---------------------------------------------------------------------------
// Kernel 2: fp16 mma.sync GEMM. CTA 128x128, BK=64, 8 warps (4M x 2N),
// warp tile 32x64. Smem rows 128B, swizzle ch^=(row&7). 3 stages x 32KB.
// One __syncthreads per mainloop iteration (top-of-loop sync is sufficient:
// prefetch into (it+2)%3 == (it-1)%3 happens only after all warps passed
// compute of stage it-1).
// ---------------------------------------------------------------------------
#define STAGE_BYTES 32768u
#define SEC_BYTES   16384u
#define NSTAGE      3

__global__ __launch_bounds__(256, 2)
void gemm_mma_kernel(const float* __restrict__ bias, float* __restrict__ C,
                     int M, int N, int K) {
    extern __shared__ char smem[];
    const uint32_t sb = smem_u32(smem);
    const int tid  = threadIdx.x;
    const int wid  = tid >> 5, lane = tid & 31;
    const int wm   = wid & 3;
    const int wn   = wid >> 2;
    const int bm   = blockIdx.x * 128, bn = blockIdx.y * 128;
    const size_t rowb = (size_t)K * 2;

    const char* pA = (const char*)g_a + (size_t)bm * rowb;
    const char* pB = (const char*)g_b + (size_t)bn * rowb;

    uint32_t sdst[4];
    int lrow[4], lch[4];
#pragma unroll
    for (int i = 0; i < 4; i++) {
        int idx = i * 256 + tid;
        lrow[i] = idx >> 3;
        lch[i]  = idx & 7;
        sdst[i] = (uint32_t)(lrow[i] * 128 + ((lch[i] ^ (lrow[i] & 7)) << 4));
    }

    float acc[2][8][4];
#pragma unroll
    for (int g = 0; g < 2; g++)
#pragma unroll
        for (int n = 0; n < 8; n++)
#pragma unroll
            for (int j = 0; j < 4; j++) acc[g][n][j] = 0.f;

    const int a_r = (lane & 15);
    const int a_cadd = (lane >> 4);
    const int b_r = (lane & 7) + ((lane >> 4) << 3);
    const int b_cadd = ((lane >> 3) & 1);

    const int nit = K >> 6;

#pragma unroll
    for (int pre = 0; pre < 2; pre++) {
        const uint32_t sbase = sb + (uint32_t)pre * STAGE_BYTES;
        const size_t kt = (size_t)pre * 128;
#pragma unroll
        for (int i = 0; i < 4; i++) {
            CP16(sbase + sdst[i],             pA + (size_t)lrow[i] * rowb + kt + lch[i] * 16);
            CP16(sbase + SEC_BYTES + sdst[i], pB + (size_t)lrow[i] * rowb + kt + lch[i] * 16);
        }
        CP_COMMIT();
    }

    for (int it = 0; it < nit; it++) {
        const uint32_t stg = sb + (uint32_t)(it % NSTAGE) * STAGE_BYTES;
        CP_WAIT1();
        __syncthreads();   // stage it ready AND all warps done with stage it-1

        if (it + 2 < nit) {
            const uint32_t sbase = sb + (uint32_t)((it + 2) % NSTAGE) * STAGE_BYTES;
            const size_t kt = (size_t)(it + 2) * 128;
#pragma unroll
            for (int i = 0; i < 4; i++) {
                CP16(sbase + sdst[i],             pA + (size_t)lrow[i] * rowb + kt + lch[i] * 16);
                CP16(sbase + SEC_BYTES + sdst[i], pB + (size_t)lrow[i] * rowb + kt + lch[i] * 16);
            }
            CP_COMMIT();
        } else {
            CP_COMMIT();
        }

#pragma unroll
        for (int s = 0; s < 4; s++) {
            uint32_t af[2][4];
#pragma unroll
            for (int g = 0; g < 2; g++) {
                int row = wm * 32 + g * 16 + a_r;
                int ch  = s * 2 + a_cadd;
                LDM4(af[g], stg + row * 128 + ((ch ^ (row & 7)) << 4));
            }
            uint32_t bf[4][4];
#pragma unroll
            for (int h = 0; h < 4; h++) {
                int row = wn * 64 + h * 16 + b_r;
                int ch  = s * 2 + b_cadd;
                LDM4(bf[h], stg + SEC_BYTES + row * 128 + ((ch ^ (row & 7)) << 4));
            }
#pragma unroll
            for (int h = 0; h < 4; h++)
#pragma unroll
                for (int g = 0; g < 2; g++) {
                    MMA_F16(acc[g][h * 2],     af[g], bf[h][0], bf[h][1]);
                    MMA_F16(acc[g][h * 2 + 1], af[g], bf[h][2], bf[h][3]);
                }
        }
        // no trailing sync: next iteration's top sync provides the ordering
    }

#pragma unroll
    for (int g = 0; g < 2; g++) {
        int row0 = bm + wm * 32 + g * 16 + (lane >> 2);
        int row1 = row0 + 8;
#pragma unroll
        for (int n = 0; n < 8; n++) {
            int col = bn + wn * 64 + n * 8 + (lane & 3) * 2;
            float2 bb = *(const float2*)&bias[col];
            if (row0 < M) {
                float2 o = make_float2(acc[g][n][0] + bb.x, acc[g][n][1] + bb.y);
                *(float2*)&C[(size_t)row0 * N + col] = o;
            }
            if (row1 < M) {
                float2 o = make_float2(acc[g][n][2] + bb.x, acc[g][n][3] + bb.y);
                *(float2*)&C[(size_t)row1 * N + col] = o;
            }
        }
    }
}

// ---------------------------------------------------------------------------
// Launch
// ---------------------------------------------------------------------------
extern "C" void kernel_launch(void* const* d_in, const int* in_sizes, int n_in,
                              void* d_out, int out_size) {
    const float* cf   = (const float*)d_in[0];
    const int* midx   = (const int*)d_in[1];
    const int* seg    = (const int*)d_in[2];
    const float* W    = (const float*)d_in[4];
    const float* bias = (const float*)d_in[5];
    float* out = (float*)d_out;

    const int N = in_sizes[5];           // 512
    const int K = in_sizes[4] / N;       // 256
    const int M = out_size / N;          // 50000
    const int num_members = in_sizes[1]; // 400000
    const int K4 = K / 4;

    cudaFuncSetAttribute(gemm_mma_kernel,
                         cudaFuncAttributeMaxDynamicSharedMemorySize,
                         (int)(NSTAGE * STAGE_BYTES));

    const int nbs = (num_members + 256) / 256;            // starts blocks
    const int nbw = (K / 32) * (N / 32);                  // prepw tiles
    prep_kernel<<<nbs + nbw, 256>>>(seg, num_members, M, W, K, N, nbs);

    mean_kernel<<<(M + 1) / 2, 128>>>((const float4*)cf, midx, K4, M);

    dim3 grid((M + 127) / 128, N / 128);
    gemm_mma_kernel<<<grid, 256, NSTAGE * STAGE_BYTES>>>(bias, out, M, N, K);
}

// round 12
// speedup vs baseline: 1.7573x; 1.0220x over previous
#include <cuda_runtime.h>
#include <cuda_fp16.h>
#include <cstdint>

// ---------------------------------------------------------------------------
// out[M,N] = segment_mean(gather(cf, member_idx), segment_ids) @ W + b
// R12 = R11 + register-fragment double-buffering in the GEMM mainloop
// (load k16-step s+1's ldmatrix frags before step s's MMAs -> LDS latency
// hides under tensor work). Rest identical to R11 (107.3 us).
// ---------------------------------------------------------------------------

#define MAX_ROWS_PAD 65664          // multiple of 128, >= padded M
#define AK 256

// Zero-initialized scratch. Rows >= M never written -> stay zero (no guards).
__device__ __half g_a[(size_t)MAX_ROWS_PAD * AK];
__device__ __half g_b[1024 * 512];          // [N][K] (W transposed)
__device__ int g_starts[65600];

// ---------------------------------------------------------------------------
// PTX helpers (baseline sm_80 features — safe through compute_103 PTX)
// ---------------------------------------------------------------------------
__device__ __forceinline__ uint32_t smem_u32(const void* p) {
    uint32_t a;
    asm("{ .reg .u64 t; cvta.to.shared.u64 t, %1; cvt.u32.u64 %0, t; }"
        : "=r"(a) : "l"(p));
    return a;
}

#define CP16(dst, src) \
    asm volatile("cp.async.cg.shared.global [%0], [%1], 16;" \
                 :: "r"(dst), "l"(src) : "memory")
#define CP_COMMIT() asm volatile("cp.async.commit_group;" ::: "memory")
#define CP_WAIT1()  asm volatile("cp.async.wait_group 1;" ::: "memory")

#define LDM4(r, a) \
    asm volatile("ldmatrix.sync.aligned.m8n8.x4.shared.b16 {%0,%1,%2,%3}, [%4];" \
                 : "=r"((r)[0]), "=r"((r)[1]), "=r"((r)[2]), "=r"((r)[3]) \
                 : "r"(a))

#define MMA_F16(d, a, b0, b1) \
    asm volatile("mma.sync.aligned.m16n8k16.row.col.f32.f16.f16.f32 " \
                 "{%0,%1,%2,%3}, {%4,%5,%6,%7}, {%8,%9}, {%0,%1,%2,%3};" \
                 : "+f"((d)[0]), "+f"((d)[1]), "+f"((d)[2]), "+f"((d)[3]) \
                 : "r"((a)[0]), "r"((a)[1]), "r"((a)[2]), "r"((a)[3]), \
                   "r"(b0), "r"(b1))

#define ACC4(a, v) { (a).x += (v).x; (a).y += (v).y; (a).z += (v).z; (a).w += (v).w; }

// ---------------------------------------------------------------------------
// Kernel 0: prep = segment starts (blocks [0, nbs)) + W prepack (rest).
// ---------------------------------------------------------------------------
__global__ void prep_kernel(const int* __restrict__ seg, int num_members, int num_cells,
                            const float* __restrict__ W, int K, int N, int nbs) {
    const int bid = blockIdx.x;
    if (bid < nbs) {
        int i = bid * 256 + threadIdx.x;
        if (i > num_members) return;
        int cur  = (i < num_members) ? __ldg(&seg[i]) : num_cells;
        int prev = (i > 0) ? __ldg(&seg[i - 1]) : -1;
        for (int c = prev + 1; c <= cur; c++) g_starts[c] = i;
        return;
    }
    __shared__ float t[32][33];
    const int b2 = bid - nbs;
    const int ktiles = K >> 5;
    const int kb = (b2 % ktiles) * 32, nb = (b2 / ktiles) * 32;
    const int tx = threadIdx.x & 31, ty = threadIdx.x >> 5;   // 32 x 8
#pragma unroll
    for (int i = 0; i < 4; i++)
        t[ty + i * 8][tx] = W[(size_t)(kb + ty + i * 8) * N + nb + tx];
    __syncthreads();
#pragma unroll
    for (int i = 0; i < 4; i++)
        g_b[(size_t)(nb + ty + i * 8) * K + kb + tx] =
            __float2half_rn(t[tx][ty + i * 8]);
}

// ---------------------------------------------------------------------------
// Kernel 1: segment mean -> fp16. 128 threads = 2 cells per block (64 each).
// Unroll-4 independent accumulator chains for gather MLP.
// ---------------------------------------------------------------------------
__global__ void mean_kernel(const float4* __restrict__ cf4,
                            const int* __restrict__ midx,
                            int K4, int M) {
    const int c = blockIdx.x * 2 + (threadIdx.x >> 6);
    if (c >= M) return;
    const int tid = threadIdx.x & 63;
    const int start = __ldg(&g_starts[c]);
    const int end   = __ldg(&g_starts[c + 1]);

    float4 a0 = make_float4(0.f, 0.f, 0.f, 0.f);
    float4 a1 = a0, a2 = a0, a3 = a0;

    int j = start;
    for (; j + 4 <= end; j += 4) {
        int i0 = __ldg(&midx[j])     * K4;
        int i1 = __ldg(&midx[j + 1]) * K4;
        int i2 = __ldg(&midx[j + 2]) * K4;
        int i3 = __ldg(&midx[j + 3]) * K4;
        float4 v0 = cf4[(size_t)i0 + tid];
        float4 v1 = cf4[(size_t)i1 + tid];
        float4 v2 = cf4[(size_t)i2 + tid];
        float4 v3 = cf4[(size_t)i3 + tid];
        ACC4(a0, v0); ACC4(a1, v1); ACC4(a2, v2); ACC4(a3, v3);
    }
    for (; j < end; j++) {
        int i0 = __ldg(&midx[j]) * K4;
        float4 v0 = cf4[(size_t)i0 + tid];
        ACC4(a0, v0);
    }

    float inv = 1.0f / fmaxf((float)(end - start), 1.0f);
    __half2 h0 = __floats2half2_rn((a0.x + a1.x + a2.x + a3.x) * inv,
                                   (a0.y + a1.y + a2.y + a3.y) * inv);
    __half2 h1 = __floats2half2_rn((a0.z + a1.z + a2.z + a3.z) * inv,
                                   (a0.w + a1.w + a2.w + a3.w) * inv);
    uint2 pk;
    pk.x = *(uint32_t*)&h0;
    pk.y = *(uint32_t*)&h1;
    ((uint2*)g_a)[(size_t)c * K4 + tid] = pk;
}

// ---------------------------------------------------------------------------
// Kernel 2: fp16 mma.sync GEMM with fragment double-buffering.
// CTA 128x128, BK=64, 8 warps (4M x 2N), warp tile 32x64.
// Smem rows 128B, swizzle ch^=(row&7). 3 stages x 32KB cp.async pipeline.
// ---------------------------------------------------------------------------
#define STAGE_BYTES 32768u
#define SEC_BYTES   16384u
#define NSTAGE      3

__global__ __launch_bounds__(256, 2)
void gemm_mma_kernel(const float* __restrict__ bias, float* __restrict__ C,
                     int M, int N, int K) {
    extern __shared__ char smem[];
    const uint32_t sb = smem_u32(smem);
    const int tid  = threadIdx.x;
    const int wid  = tid >> 5, lane = tid & 31;
    const int wm   = wid & 3;
    const int wn   = wid >> 2;
    const int bm   = blockIdx.x * 128, bn = blockIdx.y * 128;
    const size_t rowb = (size_t)K * 2;

    const char* pA = (const char*)g_a + (size_t)bm * rowb;
    const char* pB = (const char*)g_b + (size_t)bn * rowb;

    uint32_t sdst[4];
    int lrow[4], lch[4];
#pragma unroll
    for (int i = 0; i < 4; i++) {
        int idx = i * 256 + tid;
        lrow[i] = idx >> 3;
        lch[i]  = idx & 7;
        sdst[i] = (uint32_t)(lrow[i] * 128 + ((lch[i] ^ (lrow[i] & 7)) << 4));
    }

    float acc[2][8][4];
#pragma unroll
    for (int g = 0; g < 2; g++)
#pragma unroll
        for (int n = 0; n < 8; n++)
#pragma unroll
            for (int j = 0; j < 4; j++) acc[g][n][j] = 0.f;

    // precomputed ldmatrix base addresses (row part is loop-invariant)
    const int a_r = (lane & 15);
    const int a_cadd = (lane >> 4);
    const int b_r = (lane & 7) + ((lane >> 4) << 3);
    const int b_cadd = ((lane >> 3) & 1);

    const int nit = K >> 6;

#pragma unroll
    for (int pre = 0; pre < 2; pre++) {
        const uint32_t sbase = sb + (uint32_t)pre * STAGE_BYTES;
        const size_t kt = (size_t)pre * 128;
#pragma unroll
        for (int i = 0; i < 4; i++) {
            CP16(sbase + sdst[i],             pA + (size_t)lrow[i] * rowb + kt + lch[i] * 16);
            CP16(sbase + SEC_BYTES + sdst[i], pB + (size_t)lrow[i] * rowb + kt + lch[i] * 16);
        }
        CP_COMMIT();
    }

    uint32_t af[2][2][4];   // [buf][g][4]
    uint32_t bf[2][4][4];   // [buf][h][4]

    for (int it = 0; it < nit; it++) {
        const uint32_t stg = sb + (uint32_t)(it % NSTAGE) * STAGE_BYTES;
        CP_WAIT1();
        __syncthreads();   // stage it ready AND all warps done with stage it-1

        if (it + 2 < nit) {
            const uint32_t sbase = sb + (uint32_t)((it + 2) % NSTAGE) * STAGE_BYTES;
            const size_t kt = (size_t)(it + 2) * 128;
#pragma unroll
            for (int i = 0; i < 4; i++) {
                CP16(sbase + sdst[i],             pA + (size_t)lrow[i] * rowb + kt + lch[i] * 16);
                CP16(sbase + SEC_BYTES + sdst[i], pB + (size_t)lrow[i] * rowb + kt + lch[i] * 16);
            }
            CP_COMMIT();
        } else {
            CP_COMMIT();
        }

        // prime frags for s=0
#pragma unroll
        for (int g = 0; g < 2; g++) {
            int row = wm * 32 + g * 16 + a_r;
            int ch  = a_cadd;
            LDM4(af[0][g], stg + row * 128 + ((ch ^ (row & 7)) << 4));
        }
#pragma unroll
        for (int h = 0; h < 4; h++) {
            int row = wn * 64 + h * 16 + b_r;
            int ch  = b_cadd;
            LDM4(bf[0][h], stg + SEC_BYTES + row * 128 + ((ch ^ (row & 7)) << 4));
        }

#pragma unroll
        for (int s = 0; s < 4; s++) {
            const int cur = s & 1, nxt = cur ^ 1;
            if (s < 3) {
                // prefetch step s+1's frags BEFORE this step's MMAs
#pragma unroll
                for (int g = 0; g < 2; g++) {
                    int row = wm * 32 + g * 16 + a_r;
                    int ch  = (s + 1) * 2 + a_cadd;
                    LDM4(af[nxt][g], stg + row * 128 + ((ch ^ (row & 7)) << 4));
                }
#pragma unroll
                for (int h = 0; h < 4; h++) {
                    int row = wn * 64 + h * 16 + b_r;
                    int ch  = (s + 1) * 2 + b_cadd;
                    LDM4(bf[nxt][h], stg + SEC_BYTES + row * 128 + ((ch ^ (row & 7)) << 4));
                }
            }
#pragma unroll
            for (int h = 0; h < 4; h++)
#pragma unroll
                for (int g = 0; g < 2; g++) {
                    MMA_F16(acc[g][h * 2],     af[cur][g], bf[cur][h][0], bf[cur][h][1]);
                    MMA_F16(acc[g][h * 2 + 1], af[cur][g], bf[cur][h][2], bf[cur][h][3]);
                }
        }
        // no trailing sync: next iteration's top sync provides the ordering
    }

#pragma unroll
    for (int g = 0; g < 2; g++) {
        int row0 = bm + wm * 32 + g * 16 + (lane >> 2);
        int row1 = row0 + 8;
#pragma unroll
        for (int n = 0; n < 8; n++) {
            int col = bn + wn * 64 + n * 8 + (lane & 3) * 2;
            float2 bb = *(const float2*)&bias[col];
            if (row0 < M) {
                float2 o = make_float2(acc[g][n][0] + bb.x, acc[g][n][1] + bb.y);
                *(float2*)&C[(size_t)row0 * N + col] = o;
            }
            if (row1 < M) {
                float2 o = make_float2(acc[g][n][2] + bb.x, acc[g][n][3] + bb.y);
                *(float2*)&C[(size_t)row1 * N + col] = o;
            }
        }
    }
}

// ---------------------------------------------------------------------------
// Launch
// ---------------------------------------------------------------------------
extern "C" void kernel_launch(void* const* d_in, const int* in_sizes, int n_in,
                              void* d_out, int out_size) {
    const float* cf   = (const float*)d_in[0];
    const int* midx   = (const int*)d_in[1];
    const int* seg    = (const int*)d_in[2];
    const float* W    = (const float*)d_in[4];
    const float* bias = (const float*)d_in[5];
    float* out = (float*)d_out;

    const int N = in_sizes[5];           // 512
    const int K = in_sizes[4] / N;       // 256
    const int M = out_size / N;          // 50000
    const int num_members = in_sizes[1]; // 400000
    const int K4 = K / 4;

    cudaFuncSetAttribute(gemm_mma_kernel,
                         cudaFuncAttributeMaxDynamicSharedMemorySize,
                         (int)(NSTAGE * STAGE_BYTES));

    const int nbs = (num_members + 256) / 256;            // starts blocks
    const int nbw = (K / 32) * (N / 32);                  // prepw tiles
    prep_kernel<<<nbs + nbw, 256>>>(seg, num_members, M, W, K, N, nbs);

    mean_kernel<<<(M + 1) / 2, 128>>>((const float4*)cf, midx, K4, M);

    dim3 grid((M + 127) / 128, N / 128);
    gemm_mma_kernel<<<grid, 256, NSTAGE * STAGE_BYTES>>>(bias, out, M, N, K);
}